// round 2
// baseline (speedup 1.0000x reference)
#include <cuda_runtime.h>
#include <math.h>

// Problem constants
#define BATCH 2
#define CTXLEN 2048
#define DMODEL 2048
#define NHEADS 16
#define HEADDIM 128
#define MROWS (BATCH * CTXLEN)   // 4096

// Scratch (allocation-free rule: __device__ globals)
__device__ float g_q[BATCH * CTXLEN * DMODEL];
__device__ float g_k[BATCH * CTXLEN * DMODEL];
__device__ float g_v[BATCH * CTXLEN * DMODEL];
__device__ float g_ctx[BATCH * CTXLEN * DMODEL];

// ---------------------------------------------------------------------------
// SGEMM body: C[M,N] = A[M,K] @ B[K,N], row-major, 128x128 tile, K-tile 8,
// 256 threads, 8x8 per thread, double-buffered smem.
// ---------------------------------------------------------------------------
__device__ __forceinline__ void sgemm128_body(
    const float* __restrict__ A, const float* __restrict__ B,
    float* __restrict__ C, int M, int N, int K, int bx, int by)
{
    __shared__ float As[2][8][128];   // transposed: As[k][m]
    __shared__ float Bs[2][8][128];   // Bs[k][n]

    const int tid = threadIdx.x;

    const int arow = tid >> 1;            // 0..127
    const int acol = (tid & 1) * 4;       // 0 or 4
    const int brow = tid >> 5;            // 0..7
    const int bcol = (tid & 31) * 4;      // 0..124

    const float* Ag = A + (size_t)(by * 128 + arow) * K + acol;
    const float* Bg = B + (size_t)bx * 128 + bcol;

    const int row_base = (tid >> 4) * 8;  // 0..120
    const int col_base = (tid & 15) * 8;  // 0..120

    float acc[8][8];
#pragma unroll
    for (int i = 0; i < 8; i++)
#pragma unroll
        for (int j = 0; j < 8; j++) acc[i][j] = 0.0f;

    // prologue: k-tile 0 into buffer 0
    {
        float4 av = *(const float4*)(Ag);
        float4 bv = *(const float4*)(Bg + (size_t)brow * N);
        As[0][acol + 0][arow] = av.x;
        As[0][acol + 1][arow] = av.y;
        As[0][acol + 2][arow] = av.z;
        As[0][acol + 3][arow] = av.w;
        *(float4*)&Bs[0][brow][bcol] = bv;
    }
    __syncthreads();

    const int nk = K >> 3;
    for (int t = 0; t < nk; t++) {
        const int buf = t & 1;
        float4 a_n, b_n;
        const bool has_next = (t + 1 < nk);
        if (has_next) {
            a_n = *(const float4*)(Ag + (t + 1) * 8);
            b_n = *(const float4*)(Bg + (size_t)((t + 1) * 8 + brow) * N);
        }

#pragma unroll
        for (int kk = 0; kk < 8; kk++) {
            float4 a0 = *(const float4*)&As[buf][kk][row_base];
            float4 a1 = *(const float4*)&As[buf][kk][row_base + 4];
            float4 b0 = *(const float4*)&Bs[buf][kk][col_base];
            float4 b1 = *(const float4*)&Bs[buf][kk][col_base + 4];
            float ra[8] = {a0.x, a0.y, a0.z, a0.w, a1.x, a1.y, a1.z, a1.w};
            float rb[8] = {b0.x, b0.y, b0.z, b0.w, b1.x, b1.y, b1.z, b1.w};
#pragma unroll
            for (int i = 0; i < 8; i++)
#pragma unroll
                for (int j = 0; j < 8; j++)
                    acc[i][j] += ra[i] * rb[j];
        }

        if (has_next) {
            const int nbuf = buf ^ 1;
            As[nbuf][acol + 0][arow] = a_n.x;
            As[nbuf][acol + 1][arow] = a_n.y;
            As[nbuf][acol + 2][arow] = a_n.z;
            As[nbuf][acol + 3][arow] = a_n.w;
            *(float4*)&Bs[nbuf][brow][bcol] = b_n;
        }
        __syncthreads();
    }

#pragma unroll
    for (int i = 0; i < 8; i++) {
        float* Crow = C + (size_t)(by * 128 + row_base + i) * N + bx * 128 + col_base;
        *(float4*)Crow       = make_float4(acc[i][0], acc[i][1], acc[i][2], acc[i][3]);
        *(float4*)(Crow + 4) = make_float4(acc[i][4], acc[i][5], acc[i][6], acc[i][7]);
    }
}

// Plain single GEMM (output projection)
__global__ __launch_bounds__(256) void sgemm128_kernel(
    const float* __restrict__ A, const float* __restrict__ B,
    float* __restrict__ C, int M, int N, int K)
{
    sgemm128_body(A, B, C, M, N, K, blockIdx.x, blockIdx.y);
}

// Fused QKV: blockIdx.z selects {Wq->q, Wk->k, Wv->v}; shares A=x tiles via L2.
__global__ __launch_bounds__(256) void sgemm_qkv_kernel(
    const float* __restrict__ A,
    const float* __restrict__ Bq, const float* __restrict__ Bk,
    const float* __restrict__ Bv,
    float* __restrict__ Cq, float* __restrict__ Ck, float* __restrict__ Cv)
{
    const float* B = (blockIdx.z == 0) ? Bq : (blockIdx.z == 1) ? Bk : Bv;
    float*       C = (blockIdx.z == 0) ? Cq : (blockIdx.z == 1) ? Ck : Cv;
    sgemm128_body(A, B, C, MROWS, DMODEL, DMODEL, blockIdx.x, blockIdx.y);
}

// ---------------------------------------------------------------------------
// RoPE in place on q and k (blockIdx.y selects buffer). Layout (B*S, 2048).
// inv_freq is rounded to float32 first (to match the reference), then the
// angle product + mod-2pi reduction run in double so sincosf stays accurate
// at angles up to ~2048 rad.
// ---------------------------------------------------------------------------
__global__ void rope_kernel(float* __restrict__ qbuf, float* __restrict__ kbuf)
{
    int idx = blockIdx.x * blockDim.x + threadIdx.x;
    if (idx >= BATCH * CTXLEN * NHEADS * 64) return;
    float* buf = blockIdx.y ? kbuf : qbuf;

    int i = idx & 63;                 // half-dim index 0..63
    int h = (idx >> 6) & 15;
    int s = (idx >> 10) & 2047;
    int b = idx >> 21;

    float invf = (float)pow(10000.0, -(double)i * (1.0 / 64.0));  // f32 like ref
    double ang = fmod((double)s * (double)invf, 6.283185307179586476925287);
    float c, sn;
    sincosf((float)ang, &sn, &c);

    size_t base = ((size_t)(b * CTXLEN + s)) * DMODEL + h * HEADDIM + i;
    float x1 = buf[base];
    float x2 = buf[base + 64];
    buf[base]      = x1 * c - x2 * sn;
    buf[base + 64] = x2 * c + x1 * sn;
}

// ---------------------------------------------------------------------------
// Flash attention, fp32, causal, no score scaling (matches reference).
// One block = (batch, head, q-tile of 64 rows). 256 threads (16x16).
// Heavy q-tiles scheduled first (qt = 31 - blockIdx.x) to fix wave tail.
// ---------------------------------------------------------------------------
#define AT_STR 132
#define AT_PSTR 68
#define ATTN_SMEM_FLOATS (64 * AT_STR * 3 + 64 * AT_PSTR)
#define ATTN_SMEM_BYTES (ATTN_SMEM_FLOATS * 4)

__global__ __launch_bounds__(256) void attn_kernel(
    const float* __restrict__ Q, const float* __restrict__ Kg,
    const float* __restrict__ Vg, float* __restrict__ O)
{
    extern __shared__ float sm[];
    float* Qs = sm;                        // 64 x 132
    float* Ks = Qs + 64 * AT_STR;          // 64 x 132
    float* Vs = Ks + 64 * AT_STR;          // 64 x 132
    float* Ps = Vs + 64 * AT_STR;          // 64 x 68

    const int tid = threadIdx.x;
    const int qt = 31 - blockIdx.x;        // heavy tiles first
    const int h  = blockIdx.y;
    const int b  = blockIdx.z;
    const int ty = tid >> 4;               // 0..15
    const int tx = tid & 15;               // 0..15

    const float* Qb = Q + ((size_t)b * CTXLEN) * DMODEL + (size_t)h * HEADDIM;
    const float* Kb = Kg + ((size_t)b * CTXLEN) * DMODEL + (size_t)h * HEADDIM;
    const float* Vb = Vg + ((size_t)b * CTXLEN) * DMODEL + (size_t)h * HEADDIM;

    // load Q tile (64 x 128) -> shared
    for (int it = tid; it < 64 * 32; it += 256) {
        int r = it >> 5, c4 = (it & 31) * 4;
        *(float4*)&Qs[r * AT_STR + c4] =
            *(const float4*)(Qb + (size_t)(qt * 64 + r) * DMODEL + c4);
    }

    float m_i[4], l_i[4], o_acc[4][8];
#pragma unroll
    for (int i = 0; i < 4; i++) {
        m_i[i] = -1e30f;
        l_i[i] = 0.0f;
#pragma unroll
        for (int j = 0; j < 8; j++) o_acc[i][j] = 0.0f;
    }

    for (int jt = 0; jt <= qt; jt++) {
        __syncthreads();   // protects Ks/Vs reuse; orders Qs fill on first iter
        for (int it = tid; it < 64 * 32; it += 256) {
            int r = it >> 5, c4 = (it & 31) * 4;
            *(float4*)&Ks[r * AT_STR + c4] =
                *(const float4*)(Kb + (size_t)(jt * 64 + r) * DMODEL + c4);
            *(float4*)&Vs[r * AT_STR + c4] =
                *(const float4*)(Vb + (size_t)(jt * 64 + r) * DMODEL + c4);
        }
        __syncthreads();

        // S = Q K^T (4x4 per thread, full head_dim 128)
        float s[4][4];
#pragma unroll
        for (int i = 0; i < 4; i++)
#pragma unroll
            for (int j = 0; j < 4; j++) s[i][j] = 0.0f;

#pragma unroll 2
        for (int k4 = 0; k4 < 32; k4++) {
            float4 qa[4], ka[4];
#pragma unroll
            for (int i = 0; i < 4; i++)
                qa[i] = *(const float4*)&Qs[(ty * 4 + i) * AT_STR + k4 * 4];
#pragma unroll
            for (int j = 0; j < 4; j++)
                ka[j] = *(const float4*)&Ks[(tx * 4 + j) * AT_STR + k4 * 4];
#pragma unroll
            for (int i = 0; i < 4; i++)
#pragma unroll
                for (int j = 0; j < 4; j++) {
                    s[i][j] += qa[i].x * ka[j].x;
                    s[i][j] += qa[i].y * ka[j].y;
                    s[i][j] += qa[i].z * ka[j].z;
                    s[i][j] += qa[i].w * ka[j].w;
                }
        }

        if (jt == qt) {   // causal mask (diagonal tile only)
#pragma unroll
            for (int i = 0; i < 4; i++)
#pragma unroll
                for (int j = 0; j < 4; j++)
                    if (tx * 4 + j > ty * 4 + i) s[i][j] = -1e30f;
        }

        // online softmax per q-row (reduce over 16 tx lanes in half-warp)
#pragma unroll
        for (int i = 0; i < 4; i++) {
            float mx = fmaxf(fmaxf(s[i][0], s[i][1]), fmaxf(s[i][2], s[i][3]));
#pragma unroll
            for (int off = 8; off > 0; off >>= 1)
                mx = fmaxf(mx, __shfl_xor_sync(0xffffffffu, mx, off));
            float m_new = fmaxf(m_i[i], mx);

            float p0 = expf(s[i][0] - m_new);
            float p1 = expf(s[i][1] - m_new);
            float p2 = expf(s[i][2] - m_new);
            float p3 = expf(s[i][3] - m_new);
            float rs = p0 + p1 + p2 + p3;
#pragma unroll
            for (int off = 8; off > 0; off >>= 1)
                rs += __shfl_xor_sync(0xffffffffu, rs, off);

            float alpha = expf(m_i[i] - m_new);
            l_i[i] = l_i[i] * alpha + rs;
            m_i[i] = m_new;
#pragma unroll
            for (int j = 0; j < 8; j++) o_acc[i][j] *= alpha;

            float* prow = &Ps[(ty * 4 + i) * AT_PSTR + tx * 4];
            prow[0] = p0; prow[1] = p1; prow[2] = p2; prow[3] = p3;
        }
        __syncthreads();

        // O += P V (4 rows x 8 cols per thread over 64 kv)
#pragma unroll 2
        for (int kk = 0; kk < 64; kk++) {
            float4 va = *(const float4*)&Vs[kk * AT_STR + tx * 8];
            float4 vb = *(const float4*)&Vs[kk * AT_STR + tx * 8 + 4];
#pragma unroll
            for (int i = 0; i < 4; i++) {
                float p = Ps[(ty * 4 + i) * AT_PSTR + kk];
                o_acc[i][0] += p * va.x;
                o_acc[i][1] += p * va.y;
                o_acc[i][2] += p * va.z;
                o_acc[i][3] += p * va.w;
                o_acc[i][4] += p * vb.x;
                o_acc[i][5] += p * vb.y;
                o_acc[i][6] += p * vb.z;
                o_acc[i][7] += p * vb.w;
            }
        }
    }

    // normalize and write ctx in (B, S, H*Dh) layout
    float* Ob = O + ((size_t)b * CTXLEN) * DMODEL + (size_t)h * HEADDIM;
#pragma unroll
    for (int i = 0; i < 4; i++) {
        float inv = 1.0f / l_i[i];
        int r = qt * 64 + ty * 4 + i;
        float* dst = Ob + (size_t)r * DMODEL + tx * 8;
        *(float4*)dst = make_float4(o_acc[i][0] * inv, o_acc[i][1] * inv,
                                    o_acc[i][2] * inv, o_acc[i][3] * inv);
        *(float4*)(dst + 4) = make_float4(o_acc[i][4] * inv, o_acc[i][5] * inv,
                                          o_acc[i][6] * inv, o_acc[i][7] * inv);
    }
}

// ---------------------------------------------------------------------------
// Launch
// ---------------------------------------------------------------------------
extern "C" void kernel_launch(void* const* d_in, const int* in_sizes, int n_in,
                              void* d_out, int out_size)
{
    const float* x  = (const float*)d_in[0];
    const float* Wq = (const float*)d_in[1];
    const float* Wk = (const float*)d_in[2];
    const float* Wv = (const float*)d_in[3];
    const float* Wo = (const float*)d_in[4];
    float* out = (float*)d_out;

    float *q, *k, *v, *ctx;
    cudaGetSymbolAddress((void**)&q,   g_q);
    cudaGetSymbolAddress((void**)&k,   g_k);
    cudaGetSymbolAddress((void**)&v,   g_v);
    cudaGetSymbolAddress((void**)&ctx, g_ctx);

    // Fused QKV projections (z = which weight matrix)
    dim3 qkvGrid(DMODEL / 128, MROWS / 128, 3);   // (16, 32, 3)
    sgemm_qkv_kernel<<<qkvGrid, 256>>>(x, Wq, Wk, Wv, q, k, v);

    // RoPE on Q and K in one launch
    int rope_total = BATCH * CTXLEN * NHEADS * 64;
    rope_kernel<<<dim3((rope_total + 255) / 256, 2), 256>>>(q, k);

    // Attention
    cudaFuncSetAttribute(attn_kernel, cudaFuncAttributeMaxDynamicSharedMemorySize,
                         ATTN_SMEM_BYTES);
    attn_kernel<<<dim3(32, NHEADS, BATCH), 256, ATTN_SMEM_BYTES>>>(q, k, v, ctx);

    // Output projection
    dim3 gemmGrid(DMODEL / 128, MROWS / 128);     // (16, 32)
    sgemm128_kernel<<<gemmGrid, 256>>>(ctx, Wo, out, MROWS, DMODEL, DMODEL);
}

// round 14
// speedup vs baseline: 1.5826x; 1.5826x over previous
#include <cuda_runtime.h>
#include <cuda_bf16.h>
#include <math.h>
#include <stdint.h>

// Problem constants
#define BATCH 2
#define CTXLEN 2048
#define DMODEL 2048
#define NHEADS 16
#define HEADDIM 128
#define MROWS (BATCH * CTXLEN)   // 4096
#define GK DMODEL
#define GN DMODEL

// ---------------------------------------------------------------------------
// Scratch (__device__ globals: allocation-free rule)
// ---------------------------------------------------------------------------
__device__ float g_q[MROWS * DMODEL];
__device__ float g_k[MROWS * DMODEL];
__device__ float g_v[MROWS * DMODEL];
__device__ float g_ctx[MROWS * DMODEL];

__device__ float g_rope_sin[CTXLEN * 64];
__device__ float g_rope_cos[CTXLEN * 64];

__device__ __nv_bfloat16 g_xh[MROWS * GK];
__device__ __nv_bfloat16 g_xl[MROWS * GK];
__device__ __nv_bfloat16 g_ch[MROWS * GK];
__device__ __nv_bfloat16 g_cl[MROWS * GK];
// transposed weights [n][k], split
__device__ __nv_bfloat16 g_wqh[GN * GK];
__device__ __nv_bfloat16 g_wql[GN * GK];
__device__ __nv_bfloat16 g_wkh[GN * GK];
__device__ __nv_bfloat16 g_wkl[GN * GK];
__device__ __nv_bfloat16 g_wvh[GN * GK];
__device__ __nv_bfloat16 g_wvl[GN * GK];
__device__ __nv_bfloat16 g_woh[GN * GK];
__device__ __nv_bfloat16 g_wol[GN * GK];

// ---------------------------------------------------------------------------
// PTX helpers — portable (sm_80+) only: cp.async, ldmatrix, mma.sync.
// NOTHING here requires the sm_103a arch-accelerated target.
// ---------------------------------------------------------------------------
__device__ __forceinline__ uint32_t smem_u32(const void* p) {
    uint32_t a;
    asm("{ .reg .u64 t; cvta.to.shared.u64 t, %1; cvt.u32.u64 %0, t; }"
        : "=r"(a) : "l"(p));
    return a;
}
#define CP_ASYNC16(saddr, gptr)                                                \
    asm volatile("cp.async.cg.shared.global [%0], [%1], 16;"                  \
                 :: "r"(saddr), "l"(gptr) : "memory")
#define CP_COMMIT()  asm volatile("cp.async.commit_group;" ::: "memory")
#define CP_WAIT0()   asm volatile("cp.async.wait_group 0;" ::: "memory")
#define LDSM_X4(r0, r1, r2, r3, addr)                                          \
    asm volatile("ldmatrix.sync.aligned.m8n8.x4.shared.b16 {%0,%1,%2,%3}, [%4];" \
                 : "=r"(r0), "=r"(r1), "=r"(r2), "=r"(r3) : "r"(addr))
#define MMA16816(c, a, b0, b1)                                                 \
    asm volatile("mma.sync.aligned.m16n8k16.row.col.f32.bf16.bf16.f32 "       \
                 "{%0,%1,%2,%3}, {%4,%5,%6,%7}, {%8,%9}, {%0,%1,%2,%3};"      \
                 : "+f"((c)[0]), "+f"((c)[1]), "+f"((c)[2]), "+f"((c)[3])     \
                 : "r"((a)[0]), "r"((a)[1]), "r"((a)[2]), "r"((a)[3]),        \
                   "r"(b0), "r"(b1))

#define SW128(o) ((o) ^ (((o) >> 3) & 0x70))

// ---------------------------------------------------------------------------
// Split fp32 -> (hi, lo) bf16, elementwise (x and ctx)
// ---------------------------------------------------------------------------
__global__ void split_kernel(const float* __restrict__ in,
                             __nv_bfloat16* __restrict__ hi,
                             __nv_bfloat16* __restrict__ lo, int n4)
{
    int i = blockIdx.x * blockDim.x + threadIdx.x;
    if (i >= n4) return;
    float4 v = ((const float4*)in)[i];
    __nv_bfloat16 h0 = __float2bfloat16(v.x);
    __nv_bfloat16 h1 = __float2bfloat16(v.y);
    __nv_bfloat16 h2 = __float2bfloat16(v.z);
    __nv_bfloat16 h3 = __float2bfloat16(v.w);
    __nv_bfloat16 l0 = __float2bfloat16(v.x - __bfloat162float(h0));
    __nv_bfloat16 l1 = __float2bfloat16(v.y - __bfloat162float(h1));
    __nv_bfloat16 l2 = __float2bfloat16(v.z - __bfloat162float(h2));
    __nv_bfloat16 l3 = __float2bfloat16(v.w - __bfloat162float(h3));
    ((__nv_bfloat162*)hi)[2 * i]     = __nv_bfloat162(h0, h1);
    ((__nv_bfloat162*)hi)[2 * i + 1] = __nv_bfloat162(h2, h3);
    ((__nv_bfloat162*)lo)[2 * i]     = __nv_bfloat162(l0, l1);
    ((__nv_bfloat162*)lo)[2 * i + 1] = __nv_bfloat162(l2, l3);
}

// ---------------------------------------------------------------------------
// Transpose + split all 4 weights: W[k][n] fp32 -> th/tl[n][k] bf16.
// blockIdx.z selects {Wq, Wk, Wv, Wo}.
// ---------------------------------------------------------------------------
__global__ void tsplit4_kernel(
    const float* __restrict__ W0, const float* __restrict__ W1,
    const float* __restrict__ W2, const float* __restrict__ W3,
    __nv_bfloat16* __restrict__ th0, __nv_bfloat16* __restrict__ tl0,
    __nv_bfloat16* __restrict__ th1, __nv_bfloat16* __restrict__ tl1,
    __nv_bfloat16* __restrict__ th2, __nv_bfloat16* __restrict__ tl2,
    __nv_bfloat16* __restrict__ th3, __nv_bfloat16* __restrict__ tl3)
{
    const int z = blockIdx.z;
    const float* W = (z == 0) ? W0 : (z == 1) ? W1 : (z == 2) ? W2 : W3;
    __nv_bfloat16* th = (z == 0) ? th0 : (z == 1) ? th1 : (z == 2) ? th2 : th3;
    __nv_bfloat16* tl = (z == 0) ? tl0 : (z == 1) ? tl1 : (z == 2) ? tl2 : tl3;

    __shared__ float t[32][33];
    int bx = blockIdx.x;   // n tile
    int by = blockIdx.y;   // k tile
    int nx = bx * 32 + threadIdx.x;
#pragma unroll
    for (int i = 0; i < 4; i++) {
        int ky = by * 32 + threadIdx.y + i * 8;
        t[threadIdx.y + i * 8][threadIdx.x] = W[(size_t)ky * GN + nx];
    }
    __syncthreads();
    int k = by * 32 + threadIdx.x;
#pragma unroll
    for (int i = 0; i < 4; i++) {
        int n = bx * 32 + threadIdx.y + i * 8;
        float v = t[threadIdx.x][threadIdx.y + i * 8];
        __nv_bfloat16 h = __float2bfloat16(v);
        __nv_bfloat16 l = __float2bfloat16(v - __bfloat162float(h));
        th[(size_t)n * GK + k] = h;
        tl[(size_t)n * GK + k] = l;
    }
}

// ---------------------------------------------------------------------------
// Split-bf16 GEMM on mma.sync (HMMA): C tile (by,bx) of A @ B^T
//   A (hi/lo): [M, K] bf16 K-major; B (hi/lo): [N, K] bf16 K-major
//   D = Ah*Bh + Ah*Bl + Al*Bh, fp32 register accumulators.
// 128x128 CTA tile, K-chunk 64, 256 threads = 8 warps (warp tile 64x32),
// cp.async double-buffered smem tiles, SW128 swizzle for ldmatrix.
// ---------------------------------------------------------------------------
#define GT_BYTES 16384                       // one 128x64 bf16 tile
#define GEMM_SMEM (2 * 4 * GT_BYTES)         // 131072: 2 buffers x {Ah,Al,Bh,Bl}

__device__ __forceinline__ void gemm_body(
    const __nv_bfloat16* __restrict__ Ah, const __nv_bfloat16* __restrict__ Al,
    const __nv_bfloat16* __restrict__ Bh, const __nv_bfloat16* __restrict__ Bl,
    float* __restrict__ C, int bx, int by, char* sm)
{
    const uint32_t sb = smem_u32(sm);
    const int tid = threadIdx.x;
    const int lane = tid & 31, wid = tid >> 5;
    const int wm = wid & 1;        // warp row   (0..1)  -> 64 rows
    const int wn = wid >> 1;       // warp col   (0..3)  -> 32 cols

    float acc[4][4][4];
#pragma unroll
    for (int mt = 0; mt < 4; mt++)
#pragma unroll
        for (int nt = 0; nt < 4; nt++)
#pragma unroll
            for (int e = 0; e < 4; e++) acc[mt][nt][e] = 0.0f;

    const int NKT = GK / 64;   // 32 chunks

    // chunk loader: 4 tiles x 1024 x 16B over 256 threads (cp.async)
    auto issue = [&](int kt, int buf) {
        const int kbase = kt * 64;
        const uint32_t base = sb + (uint32_t)buf * 4 * GT_BYTES;
        for (int idx = tid; idx < 1024; idx += 256) {
            int r = idx >> 3, c = idx & 7;
            uint32_t so = SW128((uint32_t)(r * 128 + c * 16));
            size_t goA = (size_t)(by * 128 + r) * GK + kbase + c * 8;
            size_t goB = (size_t)(bx * 128 + r) * GK + kbase + c * 8;
            CP_ASYNC16(base + so,                Ah + goA);
            CP_ASYNC16(base + GT_BYTES + so,     Al + goA);
            CP_ASYNC16(base + 2 * GT_BYTES + so, Bh + goB);
            CP_ASYNC16(base + 3 * GT_BYTES + so, Bl + goB);
        }
        CP_COMMIT();
    };

    issue(0, 0);

    const int lrow = lane & 15;              // ldmatrix row within 16
    const int lcol = (lane >> 4) * 16;       // byte offset of 8-k half

    for (int kt = 0; kt < NKT; kt++) {
        CP_WAIT0();
        __syncthreads();                     // chunk kt landed; prior buffer free

        if (kt + 1 < NKT) issue(kt + 1, (kt + 1) & 1);

        const uint32_t tb = sb + (uint32_t)(kt & 1) * 4 * GT_BYTES;

#pragma unroll
        for (int term = 0; term < 3; term++) {
            // term 0: Ah*Bh, term 1: Ah*Bl, term 2: Al*Bh
            const uint32_t ta  = tb + ((term == 2) ? GT_BYTES : 0u);
            const uint32_t tbb = tb + 2 * GT_BYTES + ((term == 1) ? GT_BYTES : 0u);
#pragma unroll
            for (int ks = 0; ks < 4; ks++) {
                uint32_t a[4][4], b[2][4];
#pragma unroll
                for (int mt = 0; mt < 4; mt++) {
                    int row = wm * 64 + mt * 16 + lrow;
                    uint32_t ad = ta + SW128((uint32_t)(row * 128 + ks * 32 + lcol));
                    LDSM_X4(a[mt][0], a[mt][1], a[mt][2], a[mt][3], ad);
                }
#pragma unroll
                for (int nh = 0; nh < 2; nh++) {
                    int row = wn * 32 + nh * 16 + lrow;
                    uint32_t bd = tbb + SW128((uint32_t)(row * 128 + ks * 32 + lcol));
                    LDSM_X4(b[nh][0], b[nh][1], b[nh][2], b[nh][3], bd);
                }
#pragma unroll
                for (int mt = 0; mt < 4; mt++)
#pragma unroll
                    for (int nt = 0; nt < 4; nt++) {
                        const uint32_t* bh = b[nt >> 1];
                        int sel = nt & 1;    // n8 half within the 16-row ldmatrix
                        MMA16816(acc[mt][nt], a[mt], bh[sel], bh[sel + 2]);
                    }
            }
        }
    }

    // epilogue: direct float2 stores (mma c-fragment layout)
    const int group = lane >> 2, qid = lane & 3;
#pragma unroll
    for (int mt = 0; mt < 4; mt++)
#pragma unroll
        for (int nt = 0; nt < 4; nt++) {
            int row0 = by * 128 + wm * 64 + mt * 16 + group;
            int col  = bx * 128 + wn * 32 + nt * 8 + qid * 2;
            *(float2*)&C[(size_t)row0 * GN + col] =
                make_float2(acc[mt][nt][0], acc[mt][nt][1]);
            *(float2*)&C[(size_t)(row0 + 8) * GN + col] =
                make_float2(acc[mt][nt][2], acc[mt][nt][3]);
        }
}

// Single GEMM (output projection)
__global__ __launch_bounds__(256) void gemm_bf16s_kernel(
    const __nv_bfloat16* __restrict__ Ah, const __nv_bfloat16* __restrict__ Al,
    const __nv_bfloat16* __restrict__ Bh, const __nv_bfloat16* __restrict__ Bl,
    float* __restrict__ C)
{
    extern __shared__ __align__(1024) char sm[];
    gemm_body(Ah, Al, Bh, Bl, C, blockIdx.x, blockIdx.y, sm);
}

// Fused QKV GEMM: blockIdx.z picks {Wq,Wk,Wv}; shares A=x tiles via L2.
__global__ __launch_bounds__(256) void gemm_qkv_kernel(
    const __nv_bfloat16* __restrict__ Ah, const __nv_bfloat16* __restrict__ Al,
    const __nv_bfloat16* __restrict__ Bh0, const __nv_bfloat16* __restrict__ Bl0,
    const __nv_bfloat16* __restrict__ Bh1, const __nv_bfloat16* __restrict__ Bl1,
    const __nv_bfloat16* __restrict__ Bh2, const __nv_bfloat16* __restrict__ Bl2,
    float* __restrict__ C0, float* __restrict__ C1, float* __restrict__ C2)
{
    extern __shared__ __align__(1024) char sm[];
    const __nv_bfloat16* Bh = (blockIdx.z == 0) ? Bh0 : (blockIdx.z == 1) ? Bh1 : Bh2;
    const __nv_bfloat16* Bl = (blockIdx.z == 0) ? Bl0 : (blockIdx.z == 1) ? Bl1 : Bl2;
    float* C = (blockIdx.z == 0) ? C0 : (blockIdx.z == 1) ? C1 : C2;
    gemm_body(Ah, Al, Bh, Bl, C, blockIdx.x, blockIdx.y, sm);
}

// ---------------------------------------------------------------------------
// RoPE tables: one thread per (s, i) pair computes sin/cos once.
// ---------------------------------------------------------------------------
__global__ void rope_table_kernel(float* __restrict__ tsin,
                                  float* __restrict__ tcos)
{
    int idx = blockIdx.x * blockDim.x + threadIdx.x;
    if (idx >= CTXLEN * 64) return;
    int i = idx & 63;
    int s = idx >> 6;
    float invf = (float)pow(10000.0, -(double)i * (1.0 / 64.0));  // f32 like ref
    double ang = fmod((double)s * (double)invf, 6.283185307179586476925287);
    float c, sn;
    sincosf((float)ang, &sn, &c);
    tsin[idx] = sn;
    tcos[idx] = c;
}

// ---------------------------------------------------------------------------
// RoPE in place on q and k (blockIdx.y selects buffer), table-driven.
// ---------------------------------------------------------------------------
__global__ void rope_kernel(float* __restrict__ qbuf, float* __restrict__ kbuf,
                            const float* __restrict__ tsin,
                            const float* __restrict__ tcos)
{
    int idx = blockIdx.x * blockDim.x + threadIdx.x;
    if (idx >= BATCH * CTXLEN * NHEADS * 64) return;
    float* buf = blockIdx.y ? kbuf : qbuf;

    int i = idx & 63;
    int h = (idx >> 6) & 15;
    int s = (idx >> 10) & 2047;
    int b = idx >> 21;

    float sn = tsin[s * 64 + i];
    float c  = tcos[s * 64 + i];

    size_t base = ((size_t)(b * CTXLEN + s)) * DMODEL + h * HEADDIM + i;
    float x1 = buf[base];
    float x2 = buf[base + 64];
    buf[base]      = x1 * c - x2 * sn;
    buf[base + 64] = x2 * c + x1 * sn;
}

// ---------------------------------------------------------------------------
// Flash attention, fp32, causal. cp.async double-buffered K/V tiles;
// __expf softmax. K columns mapped tx+16j (2-way LDS conflicts, was 8-way).
// ---------------------------------------------------------------------------
#define AT_STR 132
#define AT_PSTR 68
#define KV_TILE (64 * AT_STR)                 // floats per K or V buffer
#define ATTN_SMEM_FLOATS (64 * AT_STR * 5 + 64 * AT_PSTR)  // Q + 2K + 2V + P
#define ATTN_SMEM_BYTES (ATTN_SMEM_FLOATS * 4)             // 186368

__global__ __launch_bounds__(256) void attn_kernel(
    const float* __restrict__ Q, const float* __restrict__ Kg,
    const float* __restrict__ Vg, float* __restrict__ O)
{
    extern __shared__ float smf[];
    float* Qs  = smf;                          // 64 x 132
    float* Ks0 = Qs + 64 * AT_STR;             // two K buffers
    float* Vs0 = Ks0 + 2 * KV_TILE;            // two V buffers
    float* Ps  = Vs0 + 2 * KV_TILE;            // 64 x 68

    const int tid = threadIdx.x;
    const int qt = 31 - blockIdx.x;            // heavy tiles first
    const int h  = blockIdx.y;
    const int b  = blockIdx.z;
    const int ty = tid >> 4;
    const int tx = tid & 15;

    const float* Qb = Q + ((size_t)b * CTXLEN) * DMODEL + (size_t)h * HEADDIM;
    const float* Kb = Kg + ((size_t)b * CTXLEN) * DMODEL + (size_t)h * HEADDIM;
    const float* Vb = Vg + ((size_t)b * CTXLEN) * DMODEL + (size_t)h * HEADDIM;

    const uint32_t ks0_a = smem_u32(Ks0);
    const uint32_t vs0_a = smem_u32(Vs0);

    // load Q tile (sync), issue async K/V loads for jt=0 into buffer 0
    for (int it = tid; it < 64 * 32; it += 256) {
        int r = it >> 5, c4 = (it & 31) * 4;
        uint32_t soff = (uint32_t)(r * AT_STR + c4) * 4;
        CP_ASYNC16(ks0_a + soff, Kb + (size_t)r * DMODEL + c4);
        CP_ASYNC16(vs0_a + soff, Vb + (size_t)r * DMODEL + c4);
        *(float4*)&Qs[r * AT_STR + c4] =
            *(const float4*)(Qb + (size_t)(qt * 64 + r) * DMODEL + c4);
    }
    CP_COMMIT();

    float m_i[4], l_i[4], o_acc[4][8];
#pragma unroll
    for (int i = 0; i < 4; i++) {
        m_i[i] = -1e30f;
        l_i[i] = 0.0f;
#pragma unroll
        for (int j = 0; j < 8; j++) o_acc[i][j] = 0.0f;
    }

    for (int jt = 0; jt <= qt; jt++) {
        CP_WAIT0();          // tile jt landed
        __syncthreads();     // all threads done with buffer jt-1 (== jt+1's target)

        // issue async loads for jt+1 into the other buffer; overlaps compute
        if (jt < qt) {
            uint32_t kd = ks0_a + (uint32_t)(((jt + 1) & 1) * KV_TILE) * 4;
            uint32_t vd = vs0_a + (uint32_t)(((jt + 1) & 1) * KV_TILE) * 4;
            const float* kg = Kb + (size_t)(jt + 1) * 64 * DMODEL;
            const float* vg = Vb + (size_t)(jt + 1) * 64 * DMODEL;
            for (int it = tid; it < 64 * 32; it += 256) {
                int r = it >> 5, c4 = (it & 31) * 4;
                uint32_t soff = (uint32_t)(r * AT_STR + c4) * 4;
                CP_ASYNC16(kd + soff, kg + (size_t)r * DMODEL + c4);
                CP_ASYNC16(vd + soff, vg + (size_t)r * DMODEL + c4);
            }
            CP_COMMIT();
        }

        const float* Ksb = Ks0 + (jt & 1) * KV_TILE;
        const float* Vsb = Vs0 + (jt & 1) * KV_TILE;

        // S = Q K^T; this thread owns K columns tx + 16*j (j = 0..3)
        float s[4][4];
#pragma unroll
        for (int i = 0; i < 4; i++)
#pragma unroll
            for (int j = 0; j < 4; j++) s[i][j] = 0.0f;

#pragma unroll 2
        for (int k4 = 0; k4 < 32; k4++) {
            float4 qa[4], ka[4];
#pragma unroll
            for (int i = 0; i < 4; i++)
                qa[i] = *(const float4*)&Qs[(ty * 4 + i) * AT_STR + k4 * 4];
#pragma unroll
            for (int j = 0; j < 4; j++)
                ka[j] = *(const float4*)&Ksb[(tx + 16 * j) * AT_STR + k4 * 4];
#pragma unroll
            for (int i = 0; i < 4; i++)
#pragma unroll
                for (int j = 0; j < 4; j++) {
                    s[i][j] += qa[i].x * ka[j].x;
                    s[i][j] += qa[i].y * ka[j].y;
                    s[i][j] += qa[i].z * ka[j].z;
                    s[i][j] += qa[i].w * ka[j].w;
                }
        }

        if (jt == qt) {   // causal mask (diagonal tile only); col = tx + 16*j
#pragma unroll
            for (int i = 0; i < 4; i++)
#pragma unroll
                for (int j = 0; j < 4; j++)
                    if (tx + 16 * j > ty * 4 + i) s[i][j] = -1e30f;
        }

#pragma unroll
        for (int i = 0; i < 4; i++) {
            float mx = fmaxf(fmaxf(s[i][0], s[i][1]), fmaxf(s[i][2], s[i][3]));
#pragma unroll
            for (int off = 8; off > 0; off >>= 1)
                mx = fmaxf(mx, __shfl_xor_sync(0xffffffffu, mx, off));
            float m_new = fmaxf(m_i[i], mx);

            float p0 = __expf(s[i][0] - m_new);
            float p1 = __expf(s[i][1] - m_new);
            float p2 = __expf(s[i][2] - m_new);
            float p3 = __expf(s[i][3] - m_new);
            float rs = p0 + p1 + p2 + p3;
#pragma unroll
            for (int off = 8; off > 0; off >>= 1)
                rs += __shfl_xor_sync(0xffffffffu, rs, off);

            float alpha = __expf(m_i[i] - m_new);
            l_i[i] = l_i[i] * alpha + rs;
            m_i[i] = m_new;
#pragma unroll
            for (int j = 0; j < 8; j++) o_acc[i][j] *= alpha;

            // scatter by true column index (stride-1 across tx: conflict-free)
            float* prow = &Ps[(ty * 4 + i) * AT_PSTR + tx];
            prow[0]  = p0;
            prow[16] = p1;
            prow[32] = p2;
            prow[48] = p3;
        }
        __syncthreads();

#pragma unroll 2
        for (int kk = 0; kk < 64; kk++) {
            float4 va = *(const float4*)&Vsb[kk * AT_STR + tx * 8];
            float4 vb = *(const float4*)&Vsb[kk * AT_STR + tx * 8 + 4];
#pragma unroll
            for (int i = 0; i < 4; i++) {
                float p = Ps[(ty * 4 + i) * AT_PSTR + kk];
                o_acc[i][0] += p * va.x;
                o_acc[i][1] += p * va.y;
                o_acc[i][2] += p * va.z;
                o_acc[i][3] += p * va.w;
                o_acc[i][4] += p * vb.x;
                o_acc[i][5] += p * vb.y;
                o_acc[i][6] += p * vb.z;
                o_acc[i][7] += p * vb.w;
            }
        }
    }

    float* Ob = O + ((size_t)b * CTXLEN) * DMODEL + (size_t)h * HEADDIM;
#pragma unroll
    for (int i = 0; i < 4; i++) {
        float inv = 1.0f / l_i[i];
        int r = qt * 64 + ty * 4 + i;
        float* dst = Ob + (size_t)r * DMODEL + tx * 8;
        *(float4*)dst = make_float4(o_acc[i][0] * inv, o_acc[i][1] * inv,
                                    o_acc[i][2] * inv, o_acc[i][3] * inv);
        *(float4*)(dst + 4) = make_float4(o_acc[i][4] * inv, o_acc[i][5] * inv,
                                          o_acc[i][6] * inv, o_acc[i][7] * inv);
    }
}

// ---------------------------------------------------------------------------
// Launch
// ---------------------------------------------------------------------------
extern "C" void kernel_launch(void* const* d_in, const int* in_sizes, int n_in,
                              void* d_out, int out_size)
{
    const float* x  = (const float*)d_in[0];
    const float* Wq = (const float*)d_in[1];
    const float* Wk = (const float*)d_in[2];
    const float* Wv = (const float*)d_in[3];
    const float* Wo = (const float*)d_in[4];
    float* out = (float*)d_out;

    float *q, *k, *v, *ctx, *tsin, *tcos;
    cudaGetSymbolAddress((void**)&q,    g_q);
    cudaGetSymbolAddress((void**)&k,    g_k);
    cudaGetSymbolAddress((void**)&v,    g_v);
    cudaGetSymbolAddress((void**)&ctx,  g_ctx);
    cudaGetSymbolAddress((void**)&tsin, g_rope_sin);
    cudaGetSymbolAddress((void**)&tcos, g_rope_cos);
    __nv_bfloat16 *xh, *xl, *ch, *cl;
    __nv_bfloat16 *wqh, *wql, *wkh, *wkl, *wvh, *wvl, *woh, *wol;
    cudaGetSymbolAddress((void**)&xh, g_xh);  cudaGetSymbolAddress((void**)&xl, g_xl);
    cudaGetSymbolAddress((void**)&ch, g_ch);  cudaGetSymbolAddress((void**)&cl, g_cl);
    cudaGetSymbolAddress((void**)&wqh, g_wqh); cudaGetSymbolAddress((void**)&wql, g_wql);
    cudaGetSymbolAddress((void**)&wkh, g_wkh); cudaGetSymbolAddress((void**)&wkl, g_wkl);
    cudaGetSymbolAddress((void**)&wvh, g_wvh); cudaGetSymbolAddress((void**)&wvl, g_wvl);
    cudaGetSymbolAddress((void**)&woh, g_woh); cudaGetSymbolAddress((void**)&wol, g_wol);

    cudaFuncSetAttribute(gemm_bf16s_kernel,
                         cudaFuncAttributeMaxDynamicSharedMemorySize, GEMM_SMEM);
    cudaFuncSetAttribute(gemm_qkv_kernel,
                         cudaFuncAttributeMaxDynamicSharedMemorySize, GEMM_SMEM);
    cudaFuncSetAttribute(attn_kernel,
                         cudaFuncAttributeMaxDynamicSharedMemorySize, ATTN_SMEM_BYTES);

    // rope tables + split input / transpose-split all weights (one launch)
    rope_table_kernel<<<(CTXLEN * 64 + 255) / 256, 256>>>(tsin, tcos);
    int n4 = MROWS * GK / 4;
    split_kernel<<<(n4 + 255) / 256, 256>>>(x, xh, xl, n4);
    dim3 tgrid(GN / 32, GK / 32, 4), tblk(32, 8);
    tsplit4_kernel<<<tgrid, tblk>>>(Wq, Wk, Wv, Wo,
                                    wqh, wql, wkh, wkl, wvh, wvl, woh, wol);

    // Fused QKV projections on tensor cores (mma.sync HMMA)
    dim3 qgrid(GN / 128, MROWS / 128, 3);   // (16, 32, 3)
    gemm_qkv_kernel<<<qgrid, 256, GEMM_SMEM>>>(xh, xl, wqh, wql, wkh, wkl,
                                               wvh, wvl, q, k, v);

    // RoPE (table-driven)
    int rope_total = BATCH * CTXLEN * NHEADS * 64;
    rope_kernel<<<dim3((rope_total + 255) / 256, 2), 256>>>(q, k, tsin, tcos);

    // attention (fp32, cp.async double-buffered)
    attn_kernel<<<dim3(32, NHEADS, BATCH), 256, ATTN_SMEM_BYTES>>>(q, k, v, ctx);

    // output projection on tensor cores
    split_kernel<<<(n4 + 255) / 256, 256>>>(ctx, ch, cl, n4);
    dim3 ggrid(GN / 128, MROWS / 128);      // (16, 32)
    gemm_bf16s_kernel<<<ggrid, 256, GEMM_SMEM>>>(ch, cl, woh, wol, out);
}